// round 9
// baseline (speedup 1.0000x reference)
#include <cuda_runtime.h>
#include <math.h>
#include <stdint.h>

#define Bb 64
#define Ss 1024
#define Ee 300
#define Hh 256
#define Gg 1024
#define DHh 512
#define DAa 64
#define Rr 16
#define MHh 512
#define RKk 8192

#define ET_OFF   0
#define PRT_OFF  3200
#define POPT_OFF 3968
#define H_OFF    4480
#define C_OFF    37248
#define PEN_OFF  70016
#define A_OFF    70017

__device__ float g_xw_f[Bb * Ss * Gg];
__device__ float g_xw_b[Bb * Ss * Gg];
__device__ float g_Wt_f[Hh * Gg];
__device__ float g_Wt_b[Hh * Gg];
__device__ float g_S1t[DHh * DAa];
__device__ float g_Hout[Bb * Ss * DHh];
__device__ float g_s2[Bb * Ss * Rr];
__device__ float g_BM[Bb * RKk];
__device__ float g_hid[3 * Bb * MHh];
__device__ float g_pp[Bb];

__device__ __forceinline__ float sigf(float x) {
    return 1.f / (1.f + expf(-x));
}

// ---- transposes: W_hh_f, W_hh_b (1024x256 -> 256x1024), S1 (64x512 -> 512x64)
__global__ void k_transpose(const float* __restrict__ Whf, const float* __restrict__ Whb,
                            const float* __restrict__ S1) {
    const float* in; float* out; int Rn, Cn;
    if (blockIdx.z == 0)      { in = Whf; out = g_Wt_f; Rn = Gg;  Cn = Hh;  }
    else if (blockIdx.z == 1) { in = Whb; out = g_Wt_b; Rn = Gg;  Cn = Hh;  }
    else                      { in = S1;  out = g_S1t;  Rn = DAa; Cn = DHh; }
    int c0 = blockIdx.x * 32, r0 = blockIdx.y * 32;
    if (c0 >= Cn || r0 >= Rn) return;
    __shared__ float tile[32][33];
    int tx = threadIdx.x, ty = threadIdx.y;   // (32,8)
#pragma unroll
    for (int i = 0; i < 4; i++)
        tile[ty + i * 8][tx] = in[(size_t)(r0 + ty + i * 8) * Cn + c0 + tx];
    __syncthreads();
#pragma unroll
    for (int i = 0; i < 4; i++)
        out[(size_t)(c0 + ty + i * 8) * Rn + r0 + tx] = tile[tx][ty + i * 8];
}

// ---- xw = emb[ids] @ W_ih^T   (M=65536, N=1024, K=300), both dirs
__global__ void __launch_bounds__(256) k_gemm_xw(const int* __restrict__ ids,
                                                 const float* __restrict__ emb,
                                                 const float* __restrict__ Wf,
                                                 const float* __restrict__ Wb) {
    const float* Wp = blockIdx.z ? Wb : Wf;
    float* out = blockIdx.z ? g_xw_b : g_xw_f;
    __shared__ float As[8][128];
    __shared__ float Bs[8][128];
    __shared__ int roff[128];
    int tid = threadIdx.x;
    int m0 = blockIdx.y * 128, n0 = blockIdx.x * 128;
    if (tid < 128) roff[tid] = ids[m0 + tid] * Ee;

    float acc[8][8];
#pragma unroll
    for (int i = 0; i < 8; i++)
#pragma unroll
        for (int j = 0; j < 8; j++) acc[i][j] = 0.f;

    int mloc = tid >> 1;
    int kloc = (tid & 1) * 4;
    int ty = tid >> 4, tx = tid & 15;
    __syncthreads();

    for (int k0 = 0; k0 < Ee; k0 += 8) {
#pragma unroll
        for (int i = 0; i < 4; i++) {
            int kk = kloc + i, kg = k0 + kk;
            As[kk][mloc] = (kg < Ee) ? emb[(size_t)roff[mloc] + kg] : 0.f;
            Bs[kk][mloc] = (kg < Ee) ? Wp[(size_t)(n0 + mloc) * Ee + kg] : 0.f;
        }
        __syncthreads();
#pragma unroll
        for (int kk = 0; kk < 8; kk++) {
            float a[8], b[8];
            *(float4*)&a[0] = *(float4*)&As[kk][ty * 8];
            *(float4*)&a[4] = *(float4*)&As[kk][ty * 8 + 4];
            *(float4*)&b[0] = *(float4*)&Bs[kk][tx * 8];
            *(float4*)&b[4] = *(float4*)&Bs[kk][tx * 8 + 4];
#pragma unroll
            for (int i = 0; i < 8; i++)
#pragma unroll
                for (int j = 0; j < 8; j++) acc[i][j] = fmaf(a[i], b[j], acc[i][j]);
        }
        __syncthreads();
    }
#pragma unroll
    for (int i = 0; i < 8; i++) {
        float* orow = out + (size_t)(m0 + ty * 8 + i) * Gg + n0 + tx * 8;
        *(float4*)orow       = make_float4(acc[i][0], acc[i][1], acc[i][2], acc[i][3]);
        *(float4*)(orow + 4) = make_float4(acc[i][4], acc[i][5], acc[i][6], acc[i][7]);
    }
}

// ---- LSTM recurrence: grid (16, 2), 512 threads, 4 batches/block
__global__ void __launch_bounds__(512) k_lstm(const float* __restrict__ h0,
                                              const float* __restrict__ c0,
                                              const int* __restrict__ len_li,
                                              float* __restrict__ dout) {
    int dir = blockIdx.y;
    int b0 = blockIdx.x * 4;
    const float* Wt = dir ? g_Wt_b : g_Wt_f;
    const float* xw = dir ? g_xw_b : g_xw_f;

    __shared__ float sh[4][Hh];
    __shared__ float sc[4][Hh];
    __shared__ float sg[4][Gg];
    __shared__ int slen[4];

    int tid = threadIdx.x;
    if (tid < 4) slen[tid] = len_li[b0 + tid];
    for (int idx = tid; idx < 4 * Hh; idx += 512) {
        int m = idx >> 8, j = idx & 255;
        sh[m][j] = h0[(size_t)(dir * Bb + b0 + m) * Hh + j];
        sc[m][j] = c0[(size_t)(dir * Bb + b0 + m) * Hh + j];
    }
    __syncthreads();
    int maxlen = max(max(slen[0], slen[1]), max(slen[2], slen[3]));
    int l[4] = {slen[0], slen[1], slen[2], slen[3]};

    int j2 = tid * 2;
    const float* wp = Wt + j2;

    for (int t = 0; t < maxlen; t++) {
        float2 acc[4];
#pragma unroll
        for (int m = 0; m < 4; m++) {
            int pos = dir ? (l[m] - 1 - t) : t;
            if (pos < 0) pos = 0;
            acc[m] = *(const float2*)&xw[((size_t)(b0 + m) * Ss + pos) * Gg + j2];
        }
#pragma unroll 4
        for (int k = 0; k < Hh; k += 4) {
            float4 h0v = *(const float4*)&sh[0][k];
            float4 h1v = *(const float4*)&sh[1][k];
            float4 h2v = *(const float4*)&sh[2][k];
            float4 h3v = *(const float4*)&sh[3][k];
            const float* hp0 = (const float*)&h0v;
            const float* hp1 = (const float*)&h1v;
            const float* hp2 = (const float*)&h2v;
            const float* hp3 = (const float*)&h3v;
#pragma unroll
            for (int kk = 0; kk < 4; kk++) {
                float2 w = *(const float2*)(wp + (size_t)(k + kk) * Gg);
                acc[0].x = fmaf(w.x, hp0[kk], acc[0].x);
                acc[0].y = fmaf(w.y, hp0[kk], acc[0].y);
                acc[1].x = fmaf(w.x, hp1[kk], acc[1].x);
                acc[1].y = fmaf(w.y, hp1[kk], acc[1].y);
                acc[2].x = fmaf(w.x, hp2[kk], acc[2].x);
                acc[2].y = fmaf(w.y, hp2[kk], acc[2].y);
                acc[3].x = fmaf(w.x, hp3[kk], acc[3].x);
                acc[3].y = fmaf(w.y, hp3[kk], acc[3].y);
            }
        }
#pragma unroll
        for (int m = 0; m < 4; m++) *(float2*)&sg[m][j2] = acc[m];
        __syncthreads();

#pragma unroll
        for (int q = 0; q < 2; q++) {
            int idx = tid + q * 512;
            int m = idx >> 8, j = idx & 255;
            int len = slen[m];
            if (t < len) {
                float gi = sg[m][j];
                float gf = sg[m][j + 256];
                float gg = sg[m][j + 512];
                float go = sg[m][j + 768];
                float cn = sigf(gf) * sc[m][j] + sigf(gi) * tanhf(gg);
                float hn = sigf(go) * tanhf(cn);
                sc[m][j] = cn;
                sh[m][j] = hn;
                int pos = dir ? (len - 1 - t) : t;
                g_Hout[((size_t)(b0 + m) * Ss + pos) * DHh + dir * Hh + j] = hn;
            }
        }
        __syncthreads();
    }
    for (int q = 0; q < 2; q++) {
        int idx = tid + q * 512;
        int m = idx >> 8, j = idx & 255;
        dout[H_OFF + (size_t)(dir * Bb + b0 + m) * Hh + j] = sh[m][j];
        dout[C_OFF + (size_t)(dir * Bb + b0 + m) * Hh + j] = sc[m][j];
    }
}

// ---- s2 = tanh(Hout @ S1^T) @ S2^T   (16 rows per block)
__global__ void __launch_bounds__(256) k_s2(const float* __restrict__ S2) {
    __shared__ float Hs[16][DHh];
    __shared__ float t1[16][DAa];
    int tid = threadIdx.x;
    size_t row0 = (size_t)blockIdx.x * 16;
    for (int idx = tid; idx < 16 * DHh / 4; idx += 256) {
        int r = idx / (DHh / 4);
        int c4 = (idx % (DHh / 4)) * 4;
        *(float4*)&Hs[r][c4] = *(const float4*)&g_Hout[(row0 + r) * DHh + c4];
    }
    __syncthreads();

    int da = tid & 63;
    int rl = tid >> 6;
    float acc[4] = {0.f, 0.f, 0.f, 0.f};
    for (int k = 0; k < DHh; k++) {
        float w = g_S1t[(size_t)k * DAa + da];
        acc[0] = fmaf(w, Hs[rl + 0][k], acc[0]);
        acc[1] = fmaf(w, Hs[rl + 4][k], acc[1]);
        acc[2] = fmaf(w, Hs[rl + 8][k], acc[2]);
        acc[3] = fmaf(w, Hs[rl + 12][k], acc[3]);
    }
    t1[rl + 0][da]  = tanhf(acc[0]);
    t1[rl + 4][da]  = tanhf(acc[1]);
    t1[rl + 8][da]  = tanhf(acc[2]);
    t1[rl + 12][da] = tanhf(acc[3]);
    __syncthreads();

    int row = tid >> 4, rh = tid & 15;
    float s = 0.f;
#pragma unroll 8
    for (int k = 0; k < DAa; k++) s = fmaf(t1[row][k], __ldg(&S2[rh * DAa + k]), s);
    g_s2[(row0 + row) * Rr + rh] = s;
}

// ---- masked softmax over t; A written to dout. grid (R, B)
__global__ void __launch_bounds__(256) k_softmax(const int* __restrict__ len_li,
                                                 float* __restrict__ dout) {
    int r = blockIdx.x, b = blockIdx.y;
    int len = len_li[b];
    int tid = threadIdx.x;
    __shared__ float red[256];

    float m = -1e30f;
    for (int t = tid; t < len; t += 256)
        m = fmaxf(m, g_s2[((size_t)b * Ss + t) * Rr + r]);
    red[tid] = m; __syncthreads();
    for (int s = 128; s > 0; s >>= 1) {
        if (tid < s) red[tid] = fmaxf(red[tid], red[tid + s]);
        __syncthreads();
    }
    float M = red[0]; __syncthreads();

    float sum = 0.f;
    for (int t = tid; t < len; t += 256)
        sum += expf(g_s2[((size_t)b * Ss + t) * Rr + r] - M);
    red[tid] = sum; __syncthreads();
    for (int s = 128; s > 0; s >>= 1) {
        if (tid < s) red[tid] += red[tid + s];
        __syncthreads();
    }
    float inv = 1.f / red[0];

    float* Aout = dout + A_OFF + ((size_t)b * Rr + r) * Ss;
    for (int t = tid; t < Ss; t += 256) {
        float a = 0.f;
        if (t < len) a = expf(g_s2[((size_t)b * Ss + t) * Rr + r] - M) * inv;
        Aout[t] = a;
    }
}

// ---- BM[b][r*512+d] = sum_t A[b,r,t]*Hout[b,t,d].  block per b, 512 thr (d)
__global__ void __launch_bounds__(512) k_M(const int* __restrict__ len_li,
                                           const float* __restrict__ dout) {
    int b = blockIdx.x;
    int tid = threadIdx.x;
    int len = len_li[b];
    __shared__ float Asm[128][16];
    float acc[16];
#pragma unroll
    for (int i = 0; i < 16; i++) acc[i] = 0.f;

    const float* Abase = dout + A_OFF + (size_t)b * Rr * Ss;
    for (int tc = 0; tc < len; tc += 128) {
        int nt = min(128, len - tc);
        for (int idx = tid; idx < 16 * 128; idx += 512) {
            int r = idx >> 7, tt = idx & 127;
            Asm[tt][r] = (tt < nt) ? Abase[(size_t)r * Ss + tc + tt] : 0.f;
        }
        __syncthreads();
        for (int tt = 0; tt < nt; tt++) {
            float hv = g_Hout[((size_t)b * Ss + tc + tt) * DHh + tid];
#pragma unroll
            for (int r2 = 0; r2 < 16; r2++)
                acc[r2] = fmaf(Asm[tt][r2], hv, acc[r2]);
        }
        __syncthreads();
    }
#pragma unroll
    for (int r2 = 0; r2 < 16; r2++)
        g_BM[(size_t)b * RKk + r2 * DHh + tid] = acc[r2];
}

// ---- AAT penal partial: block per b, thread (r,q)
__global__ void __launch_bounds__(256) k_aat(const int* __restrict__ len_li,
                                             const float* __restrict__ dout) {
    int b = blockIdx.x;
    int tid = threadIdx.x;
    int r = tid >> 4, q = tid & 15;
    int len = len_li[b];
    const float* Abase = dout + A_OFF + (size_t)b * Rr * Ss;
    float s = 0.f;
    for (int t = 0; t < len; t++)
        s = fmaf(Abase[(size_t)r * Ss + t], Abase[(size_t)q * Ss + t], s);
    float d = s - (r == q ? 1.f : 0.f);
    __shared__ float red[256];
    red[tid] = d * d; __syncthreads();
    for (int st = 128; st > 0; st >>= 1) {
        if (tid < st) red[tid] += red[tid + st];
        __syncthreads();
    }
    if (tid == 0) g_pp[b] = red[0];
}

__global__ void k_pen(float* __restrict__ dout) {
    __shared__ float red[64];
    int tid = threadIdx.x;
    red[tid] = g_pp[tid]; __syncthreads();
    for (int st = 32; st > 0; st >>= 1) {
        if (tid < st) red[tid] += red[tid + st];
        __syncthreads();
    }
    if (tid == 0) dout[PEN_OFF] = red[0] / 64.f;
}

// ---- hid[head][b][j] = relu(BM[b]·W[j] + bias[j]); warp per output
__global__ void __launch_bounds__(256) k_hid(const float* __restrict__ Wet,  const float* __restrict__ bet,
                                             const float* __restrict__ Wprt, const float* __restrict__ bprt,
                                             const float* __restrict__ Wpop, const float* __restrict__ bpop) {
    int gw = blockIdx.x * 8 + (threadIdx.x >> 5);
    int lane = threadIdx.x & 31;
    int head = gw >> 15;          // / 32768
    int rem = gw & 32767;
    int b = rem >> 9;             // / 512
    int j = rem & 511;
    const float* W; const float* bias;
    if (head == 0)      { W = Wet;  bias = bet;  }
    else if (head == 1) { W = Wprt; bias = bprt; }
    else                { W = Wpop; bias = bpop; }
    const float* bm = g_BM + (size_t)b * RKk;
    const float* wr = W + (size_t)j * RKk;
    float s = 0.f;
    for (int k = lane; k < RKk; k += 32)
        s = fmaf(bm[k], wr[k], s);
#pragma unroll
    for (int o = 16; o > 0; o >>= 1)
        s += __shfl_down_sync(0xFFFFFFFFu, s, o);
    if (lane == 0)
        g_hid[((size_t)head * Bb + b) * MHh + j] = fmaxf(s + bias[j], 0.f);
}

// ---- decode: grid (B, 3), 64 threads
__global__ void __launch_bounds__(64) k_dec(const float* __restrict__ Wdet,  const float* __restrict__ bdet,
                                            const float* __restrict__ Wdprt, const float* __restrict__ bdprt,
                                            const float* __restrict__ Wdpop, const float* __restrict__ bdpop,
                                            float* __restrict__ dout) {
    int b = blockIdx.x, head = blockIdx.y;
    int tid = threadIdx.x;
    const float* Wd; const float* bd; int N; int off;
    if (head == 0)      { Wd = Wdet;  bd = bdet;  N = 50; off = ET_OFF;   }
    else if (head == 1) { Wd = Wdprt; bd = bdprt; N = 12; off = PRT_OFF;  }
    else                { Wd = Wdpop; bd = bdpop; N = 8;  off = POPT_OFF; }
    __shared__ float sh[MHh];
    for (int k = tid; k < MHh; k += 64)
        sh[k] = g_hid[((size_t)head * Bb + b) * MHh + k];
    __syncthreads();
    if (tid < N) {
        float s = bd[tid];
        const float* wr = Wd + (size_t)tid * MHh;
        for (int k = 0; k < MHh; k++) s = fmaf(sh[k], wr[k], s);
        dout[off + b * N + tid] = s;
    }
}

extern "C" void kernel_launch(void* const* d_in, const int* in_sizes, int n_in,
                              void* d_out, int out_size) {
    const int*   ids   = (const int*)d_in[0];
    const int*   lens  = (const int*)d_in[1];
    const float* h0    = (const float*)d_in[2];
    const float* c0    = (const float*)d_in[3];
    const float* emb   = (const float*)d_in[4];
    const float* Wihf  = (const float*)d_in[5];
    const float* Whhf  = (const float*)d_in[6];
    const float* Wihb  = (const float*)d_in[7];
    const float* Whhb  = (const float*)d_in[8];
    const float* S1    = (const float*)d_in[9];
    const float* S2    = (const float*)d_in[10];
    const float* Wet   = (const float*)d_in[11];
    const float* bet   = (const float*)d_in[12];
    const float* Wdet  = (const float*)d_in[13];
    const float* bdet  = (const float*)d_in[14];
    const float* Wprt  = (const float*)d_in[15];
    const float* bprt  = (const float*)d_in[16];
    const float* Wdprt = (const float*)d_in[17];
    const float* bdprt = (const float*)d_in[18];
    const float* Wpop  = (const float*)d_in[19];
    const float* bpop  = (const float*)d_in[20];
    const float* Wdpop = (const float*)d_in[21];
    const float* bdpop = (const float*)d_in[22];
    float* dout = (float*)d_out;

    k_transpose<<<dim3(16, 32, 3), dim3(32, 8)>>>(Whhf, Whhb, S1);
    k_gemm_xw<<<dim3(8, 512, 2), 256>>>(ids, emb, Wihf, Wihb);
    k_lstm<<<dim3(16, 2), 512>>>(h0, c0, lens, dout);
    k_s2<<<4096, 256>>>(S2);
    k_softmax<<<dim3(Rr, Bb), 256>>>(lens, dout);
    k_M<<<Bb, 512>>>(lens, dout);
    k_aat<<<Bb, 256>>>(lens, dout);
    k_pen<<<1, 64>>>(dout);
    k_hid<<<12288, 256>>>(Wet, bet, Wprt, bprt, Wpop, bpop);
    k_dec<<<dim3(Bb, 3), 64>>>(Wdet, bdet, Wdprt, bdprt, Wdpop, bdpop, dout);
}

// round 10
// speedup vs baseline: 1.2059x; 1.2059x over previous
#include <cuda_runtime.h>
#include <math.h>
#include <stdint.h>

#define Bb 64
#define Ss 1024
#define Ee 300
#define Hh 256
#define Gg 1024
#define DHh 512
#define DAa 64
#define Rr 16
#define MHh 512
#define RKk 8192

#define ET_OFF   0
#define PRT_OFF  3200
#define POPT_OFF 3968
#define H_OFF    4480
#define C_OFF    37248
#define PEN_OFF  70016
#define A_OFF    70017

__device__ float g_xw_f[Bb * Ss * Gg];
__device__ float g_xw_b[Bb * Ss * Gg];
__device__ float g_Wt_f[Hh * Gg];
__device__ float g_Wt_b[Hh * Gg];
__device__ float2 g_Wt2_f[128 * Gg];   // k-pair interleaved: [p][j] = {W[2p][j], W[2p+1][j]}
__device__ float2 g_Wt2_b[128 * Gg];
__device__ float g_S1t[DHh * DAa];
__device__ float g_Hout[Bb * Ss * DHh];
__device__ float g_s2[Bb * Rr * Ss];   // layout [b][r][t]
__device__ float g_BM[Bb * RKk];
__device__ float g_hid[3 * Bb * MHh];
__device__ float g_pp[Bb];

__device__ __forceinline__ float sigf(float x) {
    return 1.f / (1.f + expf(-x));
}

__device__ __forceinline__ void ffma2(unsigned long long& d, unsigned long long a,
                                      unsigned long long b) {
    asm("fma.rn.f32x2 %0, %1, %2, %0;" : "+l"(d) : "l"(a), "l"(b));
}
__device__ __forceinline__ unsigned long long dup2(float x) {
    unsigned long long r;
    unsigned int xi = __float_as_uint(x);
    asm("mov.b64 %0, {%1, %1};" : "=l"(r) : "r"(xi));
    return r;
}
__device__ __forceinline__ float hadd2(unsigned long long v) {
    union { unsigned long long u; float2 f; } cv;
    cv.u = v;
    return cv.f.x + cv.f.y;
}

// ---- transposes: W_hh_f, W_hh_b (1024x256 -> 256x1024), S1 (64x512 -> 512x64)
__global__ void k_transpose(const float* __restrict__ Whf, const float* __restrict__ Whb,
                            const float* __restrict__ S1) {
    const float* in; float* out; int Rn, Cn;
    if (blockIdx.z == 0)      { in = Whf; out = g_Wt_f; Rn = Gg;  Cn = Hh;  }
    else if (blockIdx.z == 1) { in = Whb; out = g_Wt_b; Rn = Gg;  Cn = Hh;  }
    else                      { in = S1;  out = g_S1t;  Rn = DAa; Cn = DHh; }
    int c0 = blockIdx.x * 32, r0 = blockIdx.y * 32;
    if (c0 >= Cn || r0 >= Rn) return;
    __shared__ float tile[32][33];
    int tx = threadIdx.x, ty = threadIdx.y;
#pragma unroll
    for (int i = 0; i < 4; i++)
        tile[ty + i * 8][tx] = in[(size_t)(r0 + ty + i * 8) * Cn + c0 + tx];
    __syncthreads();
#pragma unroll
    for (int i = 0; i < 4; i++)
        out[(size_t)(c0 + ty + i * 8) * Rn + r0 + tx] = tile[tx][ty + i * 8];
}

// ---- interleave Wt rows into k-pair float2 layout
__global__ void k_interleave() {
    int j = blockIdx.x * 256 + threadIdx.x;
    int p = blockIdx.y;
    const float* Wt = blockIdx.z ? g_Wt_b : g_Wt_f;
    float2* o = blockIdx.z ? g_Wt2_b : g_Wt2_f;
    o[p * Gg + j] = make_float2(Wt[(size_t)(2 * p) * Gg + j], Wt[(size_t)(2 * p + 1) * Gg + j]);
}

// ---- xw = emb[ids] @ W_ih^T   (M=65536, N=1024, K=300), both dirs, FFMA2 micro
__global__ void __launch_bounds__(256) k_gemm_xw(const int* __restrict__ ids,
                                                 const float* __restrict__ emb,
                                                 const float* __restrict__ Wf,
                                                 const float* __restrict__ Wb) {
    const float* Wp = blockIdx.z ? Wb : Wf;
    float* out = blockIdx.z ? g_xw_b : g_xw_f;
    __shared__ __align__(16) float As[8][128];
    __shared__ __align__(16) float Bs[8][128];
    __shared__ int roff[128];
    int tid = threadIdx.x;
    int m0 = blockIdx.y * 128, n0 = blockIdx.x * 128;
    if (tid < 128) roff[tid] = ids[m0 + tid] * Ee;

    unsigned long long acc2[8][4];
#pragma unroll
    for (int i = 0; i < 8; i++)
#pragma unroll
        for (int j = 0; j < 4; j++) acc2[i][j] = 0ULL;

    int mloc = tid >> 1;
    int kloc = (tid & 1) * 4;
    int ty = tid >> 4, tx = tid & 15;
    __syncthreads();

    for (int k0 = 0; k0 < Ee; k0 += 8) {
#pragma unroll
        for (int i = 0; i < 4; i++) {
            int kk = kloc + i, kg = k0 + kk;
            As[kk][mloc] = (kg < Ee) ? emb[(size_t)roff[mloc] + kg] : 0.f;
            Bs[kk][mloc] = (kg < Ee) ? Wp[(size_t)(n0 + mloc) * Ee + kg] : 0.f;
        }
        __syncthreads();
#pragma unroll
        for (int kk = 0; kk < 8; kk++) {
            float a[8];
            *(float4*)&a[0] = *(float4*)&As[kk][ty * 8];
            *(float4*)&a[4] = *(float4*)&As[kk][ty * 8 + 4];
            unsigned long long bp[4];
            const unsigned long long* bsrc = (const unsigned long long*)&Bs[kk][tx * 8];
            bp[0] = bsrc[0]; bp[1] = bsrc[1]; bp[2] = bsrc[2]; bp[3] = bsrc[3];
#pragma unroll
            for (int i = 0; i < 8; i++) {
                unsigned long long ad = dup2(a[i]);
                ffma2(acc2[i][0], ad, bp[0]);
                ffma2(acc2[i][1], ad, bp[1]);
                ffma2(acc2[i][2], ad, bp[2]);
                ffma2(acc2[i][3], ad, bp[3]);
            }
        }
        __syncthreads();
    }
#pragma unroll
    for (int i = 0; i < 8; i++) {
        float* orow = out + (size_t)(m0 + ty * 8 + i) * Gg + n0 + tx * 8;
        ((ulonglong2*)orow)[0] = make_ulonglong2(acc2[i][0], acc2[i][1]);
        ((ulonglong2*)orow)[1] = make_ulonglong2(acc2[i][2], acc2[i][3]);
    }
}

// ---- LSTM recurrence: grid (16, 2), 512 threads, 4 batches/block, FFMA2 mainloop
__global__ void __launch_bounds__(512) k_lstm(const float* __restrict__ h0,
                                              const float* __restrict__ c0,
                                              const int* __restrict__ len_li,
                                              float* __restrict__ dout) {
    int dir = blockIdx.y;
    int b0 = blockIdx.x * 4;
    const float2* Wt2 = dir ? g_Wt2_b : g_Wt2_f;
    const float* xw = dir ? g_xw_b : g_xw_f;

    __shared__ __align__(16) float sh[4][Hh];
    __shared__ float sc[4][Hh];
    __shared__ float sg[4][Gg];
    __shared__ int slen[4];

    int tid = threadIdx.x;
    if (tid < 4) slen[tid] = len_li[b0 + tid];
    for (int idx = tid; idx < 4 * Hh; idx += 512) {
        int m = idx >> 8, j = idx & 255;
        sh[m][j] = h0[(size_t)(dir * Bb + b0 + m) * Hh + j];
        sc[m][j] = c0[(size_t)(dir * Bb + b0 + m) * Hh + j];
    }
    __syncthreads();
    int maxlen = max(max(slen[0], slen[1]), max(slen[2], slen[3]));
    int l[4] = {slen[0], slen[1], slen[2], slen[3]};

    int j2 = tid * 2;

    for (int t = 0; t < maxlen; t++) {
        float2 xv[4];
#pragma unroll
        for (int m = 0; m < 4; m++) {
            int pos = dir ? (l[m] - 1 - t) : t;
            if (pos < 0) pos = 0;
            xv[m] = *(const float2*)&xw[((size_t)(b0 + m) * Ss + pos) * Gg + j2];
        }

        unsigned long long accA[4] = {0, 0, 0, 0};
        unsigned long long accB[4] = {0, 0, 0, 0};
        for (int p0 = 0; p0 < 128; p0 += 8) {
            ulonglong2 w[8];
#pragma unroll
            for (int u = 0; u < 8; u++)
                w[u] = *(const ulonglong2*)&Wt2[(size_t)(p0 + u) * Gg + j2];
#pragma unroll
            for (int u = 0; u < 8; u++) {
#pragma unroll
                for (int m = 0; m < 4; m++) {
                    unsigned long long h2 =
                        *(const unsigned long long*)&sh[m][2 * (p0 + u)];
                    ffma2(accA[m], w[u].x, h2);
                    ffma2(accB[m], w[u].y, h2);
                }
            }
        }
#pragma unroll
        for (int m = 0; m < 4; m++) {
            sg[m][j2]     = hadd2(accA[m]) + xv[m].x;
            sg[m][j2 + 1] = hadd2(accB[m]) + xv[m].y;
        }
        __syncthreads();

#pragma unroll
        for (int q = 0; q < 2; q++) {
            int idx = tid + q * 512;
            int m = idx >> 8, j = idx & 255;
            int len = slen[m];
            if (t < len) {
                float gi = sg[m][j];
                float gf = sg[m][j + 256];
                float gg = sg[m][j + 512];
                float go = sg[m][j + 768];
                float cn = sigf(gf) * sc[m][j] + sigf(gi) * tanhf(gg);
                float hn = sigf(go) * tanhf(cn);
                sc[m][j] = cn;
                sh[m][j] = hn;
                int pos = dir ? (len - 1 - t) : t;
                g_Hout[((size_t)(b0 + m) * Ss + pos) * DHh + dir * Hh + j] = hn;
            }
        }
        __syncthreads();
    }
    for (int q = 0; q < 2; q++) {
        int idx = tid + q * 512;
        int m = idx >> 8, j = idx & 255;
        dout[H_OFF + (size_t)(dir * Bb + b0 + m) * Hh + j] = sh[m][j];
        dout[C_OFF + (size_t)(dir * Bb + b0 + m) * Hh + j] = sc[m][j];
    }
}

// ---- s2 = tanh(Hout @ S1^T) @ S2^T, write transposed [b][r][t]; skip masked tiles
__global__ void __launch_bounds__(256) k_s2(const float* __restrict__ S2,
                                            const int* __restrict__ len_li) {
    size_t row0 = (size_t)blockIdx.x * 16;
    int b = (int)(row0 >> 10);
    int t0 = (int)(row0 & 1023);
    if (t0 >= len_li[b]) return;

    __shared__ __align__(16) float Hs[16][DHh];
    __shared__ float t1[16][DAa];
    __shared__ float so[16][17];
    int tid = threadIdx.x;
    for (int idx = tid; idx < 16 * DHh / 4; idx += 256) {
        int r = idx / (DHh / 4);
        int c4 = (idx % (DHh / 4)) * 4;
        *(float4*)&Hs[r][c4] = *(const float4*)&g_Hout[(row0 + r) * DHh + c4];
    }
    __syncthreads();

    int da = tid & 63;
    int rl = tid >> 6;
    float acc[4] = {0.f, 0.f, 0.f, 0.f};
    for (int k = 0; k < DHh; k++) {
        float w = g_S1t[(size_t)k * DAa + da];
        acc[0] = fmaf(w, Hs[rl + 0][k], acc[0]);
        acc[1] = fmaf(w, Hs[rl + 4][k], acc[1]);
        acc[2] = fmaf(w, Hs[rl + 8][k], acc[2]);
        acc[3] = fmaf(w, Hs[rl + 12][k], acc[3]);
    }
    t1[rl + 0][da]  = tanhf(acc[0]);
    t1[rl + 4][da]  = tanhf(acc[1]);
    t1[rl + 8][da]  = tanhf(acc[2]);
    t1[rl + 12][da] = tanhf(acc[3]);
    __syncthreads();

    int row = tid >> 4, rh = tid & 15;
    float s = 0.f;
#pragma unroll 8
    for (int k = 0; k < DAa; k++) s = fmaf(t1[row][k], __ldg(&S2[rh * DAa + k]), s);
    so[row][rh] = s;
    __syncthreads();
    int rr = tid >> 4, tt = tid & 15;
    g_s2[((size_t)b * Rr + rr) * Ss + t0 + tt] = so[tt][rr];
}

// ---- masked softmax over t; A written to dout. grid (R, B)
__global__ void __launch_bounds__(256) k_softmax(const int* __restrict__ len_li,
                                                 float* __restrict__ dout) {
    int r = blockIdx.x, b = blockIdx.y;
    int len = len_li[b];
    int tid = threadIdx.x;
    __shared__ float red[256];
    const float* srow = g_s2 + ((size_t)b * Rr + r) * Ss;
    float* Aout = dout + A_OFF + ((size_t)b * Rr + r) * Ss;

    float m = -1e30f;
    for (int t = tid; t < len; t += 256) m = fmaxf(m, srow[t]);
    red[tid] = m; __syncthreads();
    for (int s = 128; s > 0; s >>= 1) {
        if (tid < s) red[tid] = fmaxf(red[tid], red[tid + s]);
        __syncthreads();
    }
    float M = red[0]; __syncthreads();

    float sum = 0.f;
    for (int t = tid; t < len; t += 256) {
        float e = expf(srow[t] - M);
        Aout[t] = e;
        sum += e;
    }
    red[tid] = sum; __syncthreads();
    for (int s = 128; s > 0; s >>= 1) {
        if (tid < s) red[tid] += red[tid + s];
        __syncthreads();
    }
    float inv = 1.f / red[0];

    for (int t = tid; t < Ss; t += 256)
        Aout[t] = (t < len) ? Aout[t] * inv : 0.f;
}

// ---- BM[b][r*512+d] = sum_t A[b,r,t]*Hout[b,t,d].  block per b, 512 thr (d)
__global__ void __launch_bounds__(512) k_M(const int* __restrict__ len_li,
                                           const float* __restrict__ dout) {
    int b = blockIdx.x;
    int tid = threadIdx.x;
    int len = len_li[b];
    __shared__ __align__(16) float Asm[128][16];
    float acc[16];
#pragma unroll
    for (int i = 0; i < 16; i++) acc[i] = 0.f;

    const float* Abase = dout + A_OFF + (size_t)b * Rr * Ss;
    for (int tc = 0; tc < len; tc += 128) {
        int nt = min(128, len - tc);
        for (int idx = tid; idx < 16 * 128; idx += 512) {
            int r = idx >> 7, tt = idx & 127;
            Asm[tt][r] = (tt < nt) ? Abase[(size_t)r * Ss + tc + tt] : 0.f;
        }
        __syncthreads();
        for (int tt = 0; tt < nt; tt++) {
            float hv = g_Hout[((size_t)b * Ss + tc + tt) * DHh + tid];
#pragma unroll
            for (int r2 = 0; r2 < 16; r2++)
                acc[r2] = fmaf(Asm[tt][r2], hv, acc[r2]);
        }
        __syncthreads();
    }
#pragma unroll
    for (int r2 = 0; r2 < 16; r2++)
        g_BM[(size_t)b * RKk + r2 * DHh + tid] = acc[r2];
}

// ---- AAT penal partial (smem-chunked): block per b, thread (r,q)
__global__ void __launch_bounds__(256) k_aat(const int* __restrict__ len_li,
                                             const float* __restrict__ dout) {
    int b = blockIdx.x;
    int tid = threadIdx.x;
    int r = tid >> 4, q = tid & 15;
    int len = len_li[b];
    const float* Abase = dout + A_OFF + (size_t)b * Rr * Ss;
    __shared__ float As2[16][257];
    float s = 0.f;
    for (int tc = 0; tc < len; tc += 256) {
        int nt = min(256, len - tc);
        for (int i = tid; i < 16 * 256; i += 256) {
            int rr = i >> 8, tt = i & 255;
            As2[rr][tt] = (tt < nt) ? Abase[(size_t)rr * Ss + tc + tt] : 0.f;
        }
        __syncthreads();
#pragma unroll 4
        for (int tt = 0; tt < 256; tt++)
            s = fmaf(As2[r][tt], As2[q][tt], s);
        __syncthreads();
    }
    float d = s - (r == q ? 1.f : 0.f);
    __shared__ float red[256];
    red[tid] = d * d; __syncthreads();
    for (int st = 128; st > 0; st >>= 1) {
        if (tid < st) red[tid] += red[tid + st];
        __syncthreads();
    }
    if (tid == 0) g_pp[b] = red[0];
}

__global__ void k_pen(float* __restrict__ dout) {
    __shared__ float red[64];
    int tid = threadIdx.x;
    red[tid] = g_pp[tid]; __syncthreads();
    for (int st = 32; st > 0; st >>= 1) {
        if (tid < st) red[tid] += red[tid + st];
        __syncthreads();
    }
    if (tid == 0) dout[PEN_OFF] = red[0] / 64.f;
}

// ---- hid = relu(BM @ W^T + b): tiled GEMM, 96 blocks of 16 rows x 64 batch
__global__ void __launch_bounds__(256) k_hid(const float* __restrict__ Wet,  const float* __restrict__ bet,
                                             const float* __restrict__ Wprt, const float* __restrict__ bprt,
                                             const float* __restrict__ Wpop, const float* __restrict__ bpop) {
    int blk = blockIdx.x;
    int head = blk >> 5;          // 32 blocks per head
    int j0 = (blk & 31) * 16;
    const float* W    = (head == 0) ? Wet : (head == 1) ? Wprt : Wpop;
    const float* bias = (head == 0) ? bet : (head == 1) ? bprt : bpop;
    __shared__ float Ws[16][64];
    __shared__ float Bs[64][65];
    int tid = threadIdx.x;
    int rj = tid >> 4;
    int bq = (tid & 15) * 4;
    float acc[4] = {0.f, 0.f, 0.f, 0.f};
    for (int kc = 0; kc < RKk; kc += 64) {
        for (int i = tid; i < 1024; i += 256) {
            int r = i >> 6, k = i & 63;
            Ws[r][k] = W[(size_t)(j0 + r) * RKk + kc + k];
        }
        for (int i = tid; i < 4096; i += 256) {
            int bx = i >> 6, k = i & 63;
            Bs[bx][k] = g_BM[(size_t)bx * RKk + kc + k];
        }
        __syncthreads();
#pragma unroll 4
        for (int k = 0; k < 64; k++) {
            float w = Ws[rj][k];
            acc[0] = fmaf(w, Bs[bq + 0][k], acc[0]);
            acc[1] = fmaf(w, Bs[bq + 1][k], acc[1]);
            acc[2] = fmaf(w, Bs[bq + 2][k], acc[2]);
            acc[3] = fmaf(w, Bs[bq + 3][k], acc[3]);
        }
        __syncthreads();
    }
    float bv = bias[j0 + rj];
#pragma unroll
    for (int q = 0; q < 4; q++)
        g_hid[((size_t)head * Bb + bq + q) * MHh + j0 + rj] = fmaxf(acc[q] + bv, 0.f);
}

// ---- decode: grid (B, 3), 64 threads
__global__ void __launch_bounds__(64) k_dec(const float* __restrict__ Wdet,  const float* __restrict__ bdet,
                                            const float* __restrict__ Wdprt, const float* __restrict__ bdprt,
                                            const float* __restrict__ Wdpop, const float* __restrict__ bdpop,
                                            float* __restrict__ dout) {
    int b = blockIdx.x, head = blockIdx.y;
    int tid = threadIdx.x;
    const float* Wd; const float* bd; int N; int off;
    if (head == 0)      { Wd = Wdet;  bd = bdet;  N = 50; off = ET_OFF;   }
    else if (head == 1) { Wd = Wdprt; bd = bdprt; N = 12; off = PRT_OFF;  }
    else                { Wd = Wdpop; bd = bdpop; N = 8;  off = POPT_OFF; }
    __shared__ float sh[MHh];
    for (int k = tid; k < MHh; k += 64)
        sh[k] = g_hid[((size_t)head * Bb + b) * MHh + k];
    __syncthreads();
    if (tid < N) {
        float s = bd[tid];
        const float* wr = Wd + (size_t)tid * MHh;
        for (int k = 0; k < MHh; k++) s = fmaf(sh[k], wr[k], s);
        dout[off + b * N + tid] = s;
    }
}

extern "C" void kernel_launch(void* const* d_in, const int* in_sizes, int n_in,
                              void* d_out, int out_size) {
    const int*   ids   = (const int*)d_in[0];
    const int*   lens  = (const int*)d_in[1];
    const float* h0    = (const float*)d_in[2];
    const float* c0    = (const float*)d_in[3];
    const float* emb   = (const float*)d_in[4];
    const float* Wihf  = (const float*)d_in[5];
    const float* Whhf  = (const float*)d_in[6];
    const float* Wihb  = (const float*)d_in[7];
    const float* Whhb  = (const float*)d_in[8];
    const float* S1    = (const float*)d_in[9];
    const float* S2    = (const float*)d_in[10];
    const float* Wet   = (const float*)d_in[11];
    const float* bet   = (const float*)d_in[12];
    const float* Wdet  = (const float*)d_in[13];
    const float* bdet  = (const float*)d_in[14];
    const float* Wprt  = (const float*)d_in[15];
    const float* bprt  = (const float*)d_in[16];
    const float* Wdprt = (const float*)d_in[17];
    const float* bdprt = (const float*)d_in[18];
    const float* Wpop  = (const float*)d_in[19];
    const float* bpop  = (const float*)d_in[20];
    const float* Wdpop = (const float*)d_in[21];
    const float* bdpop = (const float*)d_in[22];
    float* dout = (float*)d_out;

    k_transpose<<<dim3(16, 32, 3), dim3(32, 8)>>>(Whhf, Whhb, S1);
    k_interleave<<<dim3(4, 128, 2), 256>>>();
    k_gemm_xw<<<dim3(8, 512, 2), 256>>>(ids, emb, Wihf, Wihb);
    k_lstm<<<dim3(16, 2), 512>>>(h0, c0, lens, dout);
    k_s2<<<4096, 256>>>(S2, lens);
    k_softmax<<<dim3(Rr, Bb), 256>>>(lens, dout);
    k_M<<<Bb, 512>>>(lens, dout);
    k_aat<<<Bb, 256>>>(lens, dout);
    k_pen<<<1, 64>>>(dout);
    k_hid<<<96, 256>>>(Wet, bet, Wprt, bprt, Wpop, bpop);
    k_dec<<<dim3(Bb, 3), 64>>>(Wdet, bdet, Wdprt, bdprt, Wdpop, bdpop, dout);
}

// round 11
// speedup vs baseline: 2.2971x; 1.9048x over previous
#include <cuda_runtime.h>
#include <math.h>
#include <stdint.h>

#define Bb 64
#define Ss 1024
#define Ee 300
#define Hh 256
#define Gg 1024
#define DHh 512
#define DAa 64
#define Rr 16
#define MHh 512
#define RKk 8192

#define ET_OFF   0
#define PRT_OFF  3200
#define POPT_OFF 3968
#define H_OFF    4480
#define C_OFF    37248
#define PEN_OFF  70016
#define A_OFF    70017

__device__ float g_xw_f[Bb * Ss * Gg];
__device__ float g_xw_b[Bb * Ss * Gg];
__device__ float g_S1t[DHh * DAa];
__device__ float g_Hout[Bb * Ss * DHh];
__device__ float g_s2[Bb * Rr * Ss];   // [b][r][t]
__device__ float g_BM[Bb * RKk];
__device__ float g_hid[3 * Bb * MHh];
__device__ float g_pp[Bb];

__device__ __forceinline__ float sigf(float x) {
    return 1.f / (1.f + expf(-x));
}
__device__ __forceinline__ void ffma2(unsigned long long& d, unsigned long long a,
                                      unsigned long long b) {
    asm("fma.rn.f32x2 %0, %1, %2, %0;" : "+l"(d) : "l"(a), "l"(b));
}
__device__ __forceinline__ unsigned long long pack2(float x, float y) {
    unsigned long long r;
    asm("mov.b64 %0, {%1, %2};" : "=l"(r) : "r"(__float_as_uint(x)), "r"(__float_as_uint(y)));
    return r;
}
__device__ __forceinline__ float hadd2(unsigned long long v) {
    union { unsigned long long u; float2 f; } cv;
    cv.u = v;
    return cv.f.x + cv.f.y;
}
__device__ __forceinline__ uint32_t smem_u32(const void* p) {
    return (uint32_t)__cvta_generic_to_shared(p);
}
__device__ __forceinline__ uint32_t mapa_u32(uint32_t a, uint32_t r) {
    uint32_t o;
    asm("mapa.shared::cluster.u32 %0, %1, %2;" : "=r"(o) : "r"(a), "r"(r));
    return o;
}
__device__ __forceinline__ void stc_f32(uint32_t a, float v) {
    asm volatile("st.shared::cluster.f32 [%0], %1;" :: "r"(a), "f"(v) : "memory");
}
#define CLUSTER_SYNC() do { \
    asm volatile("barrier.cluster.arrive.aligned;" ::: "memory"); \
    asm volatile("barrier.cluster.wait.aligned;" ::: "memory"); \
} while (0)

// ---- S1 transpose only (64x512 -> 512x64)
__global__ void k_transpose(const float* __restrict__ S1) {
    int c0 = blockIdx.x * 32, r0 = blockIdx.y * 32;
    __shared__ float tile[32][33];
    int tx = threadIdx.x, ty = threadIdx.y;
#pragma unroll
    for (int i = 0; i < 4; i++)
        tile[ty + i * 8][tx] = S1[(size_t)(r0 + ty + i * 8) * DHh + c0 + tx];
    __syncthreads();
#pragma unroll
    for (int i = 0; i < 4; i++)
        g_S1t[(size_t)(c0 + ty + i * 8) * DAa + r0 + tx] = tile[tx][ty + i * 8];
}

// ---- xw = emb[ids] @ W_ih^T (M=65536, N=1024, K=300), both dirs; skip masked tiles
__global__ void __launch_bounds__(256) k_gemm_xw(const int* __restrict__ ids,
                                                 const float* __restrict__ emb,
                                                 const float* __restrict__ Wf,
                                                 const float* __restrict__ Wb,
                                                 const int* __restrict__ len_li) {
    int m0 = blockIdx.y * 128, n0 = blockIdx.x * 128;
    {
        int b = m0 >> 10, t0 = m0 & 1023;
        if (t0 >= len_li[b]) return;
    }
    const float* Wp = blockIdx.z ? Wb : Wf;
    float* out = blockIdx.z ? g_xw_b : g_xw_f;
    __shared__ __align__(16) float As[8][128];
    __shared__ __align__(16) float Bs[8][128];
    __shared__ int roff[128];
    int tid = threadIdx.x;
    if (tid < 128) roff[tid] = ids[m0 + tid] * Ee;

    unsigned long long acc2[8][4];
#pragma unroll
    for (int i = 0; i < 8; i++)
#pragma unroll
        for (int j = 0; j < 4; j++) acc2[i][j] = 0ULL;

    int mloc = tid >> 1;
    int kloc = (tid & 1) * 4;
    int ty = tid >> 4, tx = tid & 15;
    __syncthreads();

    for (int k0 = 0; k0 < Ee; k0 += 8) {
#pragma unroll
        for (int i = 0; i < 4; i++) {
            int kk = kloc + i, kg = k0 + kk;
            As[kk][mloc] = (kg < Ee) ? emb[(size_t)roff[mloc] + kg] : 0.f;
            Bs[kk][mloc] = (kg < Ee) ? Wp[(size_t)(n0 + mloc) * Ee + kg] : 0.f;
        }
        __syncthreads();
#pragma unroll
        for (int kk = 0; kk < 8; kk++) {
            float a[8];
            *(float4*)&a[0] = *(float4*)&As[kk][ty * 8];
            *(float4*)&a[4] = *(float4*)&As[kk][ty * 8 + 4];
            unsigned long long bp[4];
            const unsigned long long* bsrc = (const unsigned long long*)&Bs[kk][tx * 8];
            bp[0] = bsrc[0]; bp[1] = bsrc[1]; bp[2] = bsrc[2]; bp[3] = bsrc[3];
#pragma unroll
            for (int i = 0; i < 8; i++) {
                unsigned long long ad = pack2(a[i], a[i]);
                ffma2(acc2[i][0], ad, bp[0]);
                ffma2(acc2[i][1], ad, bp[1]);
                ffma2(acc2[i][2], ad, bp[2]);
                ffma2(acc2[i][3], ad, bp[3]);
            }
        }
        __syncthreads();
    }
#pragma unroll
    for (int i = 0; i < 8; i++) {
        float* orow = out + (size_t)(m0 + ty * 8 + i) * Gg + n0 + tx * 8;
        ((ulonglong2*)orow)[0] = make_ulonglong2(acc2[i][0], acc2[i][1]);
        ((ulonglong2*)orow)[1] = make_ulonglong2(acc2[i][2], acc2[i][3]);
    }
}

// ---- LSTM recurrence: cluster of 8 CTAs per 8 batches, W slice resident in smem.
// grid (64, 2), cluster (8,1,1), 256 threads.
// smem: Wv4 [64 pp][128 cc] float4 (128KB) | hbuf [2][8][256] (16KB) | sg [128][9] (4.5KB)
#define LSTM_SMEM_FLOATS (32768 + 4096 + 1152)
__global__ void __launch_bounds__(256, 1) __cluster_dims__(8, 1, 1)
k_lstm(const float* __restrict__ Whf, const float* __restrict__ Whb,
       const float* __restrict__ h0, const float* __restrict__ c0,
       const int* __restrict__ len_li, float* __restrict__ dout) {
    extern __shared__ float smem[];
    float4* Wv = (float4*)smem;              // [pp*128 + cc]
    float* hb = smem + 32768;                // [buf*2048 + b*256 + j]
    float* sg = smem + 32768 + 4096;         // [cc*9 + b]
    __shared__ int slen[8];

    int tid = threadIdx.x;
    int dir = blockIdx.y;
    int rank = blockIdx.x & 7;
    int b0 = (blockIdx.x >> 3) * 8;
    int j0 = rank * 32;
    const float* Whh = dir ? Whb : Whf;
    const float* xw  = dir ? g_xw_b : g_xw_f;

    // load W rows for this CTA's 128 gate columns
    for (int i = tid; i < 128 * 64; i += 256) {
        int cc = i >> 6, pp = i & 63;
        int gcol = (cc >> 5) * 256 + j0 + (cc & 31);
        Wv[pp * 128 + cc] = *(const float4*)&Whh[(size_t)gcol * Hh + pp * 4];
    }
    // load full h0 for 8 batches into buffer 0
    for (int i = tid; i < 8 * Hh; i += 256)
        hb[i] = h0[(size_t)(dir * Bb + b0) * Hh + i];
    if (tid < 8) slen[tid] = len_li[b0 + tid];
    __syncthreads();

    int maxlen = 0;
#pragma unroll
    for (int i = 0; i < 8; i++) maxlen = max(maxlen, slen[i]);

    // phase-B persistent state: thread -> (batch pb, dim j0+pj)
    int pb = tid >> 5, pj = tid & 31;
    int plen = slen[pb];
    float creg = c0[(size_t)(dir * Bb + b0 + pb) * Hh + j0 + pj];
    float hreg = hb[pb * Hh + j0 + pj];

    // phase-A mapping: thread -> (batch group g, column cc)
    int g = tid >> 7;            // 0/1 -> batches 4g..4g+3
    int cc = tid & 127;
    int gcol = (cc >> 5) * 256 + j0 + (cc & 31);
    int alen[4];
#pragma unroll
    for (int m = 0; m < 4; m++) alen[m] = slen[4 * g + m];
    const float4* wcol = Wv + cc;
    const float* xwb = xw + ((size_t)(b0 + 4 * g) * Ss) * Gg + gcol;

    // DSMEM peer addresses of hb
    uint32_t hb_u = smem_u32(hb);
    uint32_t peer[8];
#pragma unroll
    for (int r = 0; r < 8; r++) peer[r] = mapa_u32(hb_u, (uint32_t)r);

    CLUSTER_SYNC();

    int cur = 0;
    for (int t = 0; t < maxlen; t++) {
        // gate bias from xw (tail reads hit zero-init scratch; values discarded)
        float xv[4];
#pragma unroll
        for (int m = 0; m < 4; m++) {
            int pos = dir ? alen[m] - 1 - t : t;
            if (pos < 0) pos = 0;
            xv[m] = __ldg(xwb + ((size_t)m * Ss + pos) * Gg);
        }
        // dot: gates[4 batches][my col] over k=256
        unsigned long long acc[4] = {0ULL, 0ULL, 0ULL, 0ULL};
        const float* hc = hb + cur * 2048 + g * 4 * Hh;
#pragma unroll 16
        for (int pp = 0; pp < 64; pp++) {
            float4 w = wcol[pp * 128];
            unsigned long long wlo = pack2(w.x, w.y);
            unsigned long long whi = pack2(w.z, w.w);
#pragma unroll
            for (int m = 0; m < 4; m++) {
                float4 h4 = *(const float4*)&hc[m * Hh + pp * 4];
                ffma2(acc[m], wlo, pack2(h4.x, h4.y));
                ffma2(acc[m], whi, pack2(h4.z, h4.w));
            }
        }
#pragma unroll
        for (int m = 0; m < 4; m++)
            sg[cc * 9 + 4 * g + m] = hadd2(acc[m]) + xv[m];
        __syncthreads();

        // nonlinearity + state update for (pb, j0+pj)
        {
            float gi = sg[(pj) * 9 + pb];
            float gf = sg[(32 + pj) * 9 + pb];
            float gg = sg[(64 + pj) * 9 + pb];
            float go = sg[(96 + pj) * 9 + pb];
            if (t < plen) {
                creg = sigf(gf) * creg + sigf(gi) * tanhf(gg);
                hreg = sigf(go) * tanhf(creg);
                int pos = dir ? plen - 1 - t : t;
                g_Hout[((size_t)(b0 + pb) * Ss + pos) * DHh + dir * Hh + j0 + pj] = hreg;
            }
            uint32_t off = (uint32_t)(((cur ^ 1) * 2048 + pb * Hh + j0 + pj) * 4);
#pragma unroll
            for (int r = 0; r < 8; r++) stc_f32(peer[r] + off, hreg);
        }
        CLUSTER_SYNC();
        cur ^= 1;
    }
    dout[H_OFF + (size_t)(dir * Bb + b0 + pb) * Hh + j0 + pj] = hreg;
    dout[C_OFF + (size_t)(dir * Bb + b0 + pb) * Hh + j0 + pj] = creg;
}

// ---- s2 = tanh(Hout @ S1^T) @ S2^T, write [b][r][t]; skip masked tiles
__global__ void __launch_bounds__(256) k_s2(const float* __restrict__ S2,
                                            const int* __restrict__ len_li) {
    size_t row0 = (size_t)blockIdx.x * 16;
    int b = (int)(row0 >> 10);
    int t0 = (int)(row0 & 1023);
    if (t0 >= len_li[b]) return;

    __shared__ __align__(16) float Hs[16][DHh];
    __shared__ float t1[16][DAa];
    __shared__ float so[16][17];
    int tid = threadIdx.x;
    for (int idx = tid; idx < 16 * DHh / 4; idx += 256) {
        int r = idx / (DHh / 4);
        int c4 = (idx % (DHh / 4)) * 4;
        *(float4*)&Hs[r][c4] = *(const float4*)&g_Hout[(row0 + r) * DHh + c4];
    }
    __syncthreads();

    int da = tid & 63;
    int rl = tid >> 6;
    float acc[4] = {0.f, 0.f, 0.f, 0.f};
    for (int k = 0; k < DHh; k++) {
        float w = g_S1t[(size_t)k * DAa + da];
        acc[0] = fmaf(w, Hs[rl + 0][k], acc[0]);
        acc[1] = fmaf(w, Hs[rl + 4][k], acc[1]);
        acc[2] = fmaf(w, Hs[rl + 8][k], acc[2]);
        acc[3] = fmaf(w, Hs[rl + 12][k], acc[3]);
    }
    t1[rl + 0][da]  = tanhf(acc[0]);
    t1[rl + 4][da]  = tanhf(acc[1]);
    t1[rl + 8][da]  = tanhf(acc[2]);
    t1[rl + 12][da] = tanhf(acc[3]);
    __syncthreads();

    int row = tid >> 4, rh = tid & 15;
    float s = 0.f;
#pragma unroll 8
    for (int k = 0; k < DAa; k++) s = fmaf(t1[row][k], __ldg(&S2[rh * DAa + k]), s);
    so[row][rh] = s;
    __syncthreads();
    int rr = tid >> 4, tt = tid & 15;
    g_s2[((size_t)b * Rr + rr) * Ss + t0 + tt] = so[tt][rr];
}

// ---- masked softmax over t; A written to dout. grid (R, B)
__global__ void __launch_bounds__(256) k_softmax(const int* __restrict__ len_li,
                                                 float* __restrict__ dout) {
    int r = blockIdx.x, b = blockIdx.y;
    int len = len_li[b];
    int tid = threadIdx.x;
    __shared__ float red[256];
    const float* srow = g_s2 + ((size_t)b * Rr + r) * Ss;
    float* Aout = dout + A_OFF + ((size_t)b * Rr + r) * Ss;

    float m = -1e30f;
    for (int t = tid; t < len; t += 256) m = fmaxf(m, srow[t]);
    red[tid] = m; __syncthreads();
    for (int s = 128; s > 0; s >>= 1) {
        if (tid < s) red[tid] = fmaxf(red[tid], red[tid + s]);
        __syncthreads();
    }
    float M = red[0]; __syncthreads();

    float sum = 0.f;
    for (int t = tid; t < len; t += 256) {
        float e = expf(srow[t] - M);
        Aout[t] = e;
        sum += e;
    }
    red[tid] = sum; __syncthreads();
    for (int s = 128; s > 0; s >>= 1) {
        if (tid < s) red[tid] += red[tid + s];
        __syncthreads();
    }
    float inv = 1.f / red[0];

    for (int t = tid; t < Ss; t += 256)
        Aout[t] = (t < len) ? Aout[t] * inv : 0.f;
}

// ---- BM = A @ Hout. block per b, 512 thr (d)
__global__ void __launch_bounds__(512) k_M(const int* __restrict__ len_li,
                                           const float* __restrict__ dout) {
    int b = blockIdx.x;
    int tid = threadIdx.x;
    int len = len_li[b];
    __shared__ __align__(16) float Asm[128][16];
    float acc[16];
#pragma unroll
    for (int i = 0; i < 16; i++) acc[i] = 0.f;

    const float* Abase = dout + A_OFF + (size_t)b * Rr * Ss;
    for (int tc = 0; tc < len; tc += 128) {
        int nt = min(128, len - tc);
        for (int idx = tid; idx < 16 * 128; idx += 512) {
            int r = idx >> 7, tt = idx & 127;
            Asm[tt][r] = (tt < nt) ? Abase[(size_t)r * Ss + tc + tt] : 0.f;
        }
        __syncthreads();
        for (int tt = 0; tt < nt; tt++) {
            float hv = g_Hout[((size_t)b * Ss + tc + tt) * DHh + tid];
#pragma unroll
            for (int r2 = 0; r2 < 16; r2++)
                acc[r2] = fmaf(Asm[tt][r2], hv, acc[r2]);
        }
        __syncthreads();
    }
#pragma unroll
    for (int r2 = 0; r2 < 16; r2++)
        g_BM[(size_t)b * RKk + r2 * DHh + tid] = acc[r2];
}

// ---- AAT penal partial. block per b, thread (r,q)
__global__ void __launch_bounds__(256) k_aat(const int* __restrict__ len_li,
                                             const float* __restrict__ dout) {
    int b = blockIdx.x;
    int tid = threadIdx.x;
    int r = tid >> 4, q = tid & 15;
    int len = len_li[b];
    const float* Abase = dout + A_OFF + (size_t)b * Rr * Ss;
    __shared__ float As2[16][257];
    float s = 0.f;
    for (int tc = 0; tc < len; tc += 256) {
        int nt = min(256, len - tc);
        for (int i = tid; i < 16 * 256; i += 256) {
            int rr = i >> 8, tt = i & 255;
            As2[rr][tt] = (tt < nt) ? Abase[(size_t)rr * Ss + tc + tt] : 0.f;
        }
        __syncthreads();
#pragma unroll 4
        for (int tt = 0; tt < 256; tt++)
            s = fmaf(As2[r][tt], As2[q][tt], s);
        __syncthreads();
    }
    float d = s - (r == q ? 1.f : 0.f);
    __shared__ float red[256];
    red[tid] = d * d; __syncthreads();
    for (int st = 128; st > 0; st >>= 1) {
        if (tid < st) red[tid] += red[tid + st];
        __syncthreads();
    }
    if (tid == 0) g_pp[b] = red[0];
}

__global__ void k_pen(float* __restrict__ dout) {
    __shared__ float red[64];
    int tid = threadIdx.x;
    red[tid] = g_pp[tid]; __syncthreads();
    for (int st = 32; st > 0; st >>= 1) {
        if (tid < st) red[tid] += red[tid + st];
        __syncthreads();
    }
    if (tid == 0) dout[PEN_OFF] = red[0] / 64.f;
}

// ---- hid = relu(BM @ W^T + b): tiled GEMM, 96 blocks
__global__ void __launch_bounds__(256) k_hid(const float* __restrict__ Wet,  const float* __restrict__ bet,
                                             const float* __restrict__ Wprt, const float* __restrict__ bprt,
                                             const float* __restrict__ Wpop, const float* __restrict__ bpop) {
    int blk = blockIdx.x;
    int head = blk >> 5;
    int j0 = (blk & 31) * 16;
    const float* W    = (head == 0) ? Wet : (head == 1) ? Wprt : Wpop;
    const float* bias = (head == 0) ? bet : (head == 1) ? bprt : bpop;
    __shared__ float Ws[16][64];
    __shared__ float Bs[64][65];
    int tid = threadIdx.x;
    int rj = tid >> 4;
    int bq = (tid & 15) * 4;
    float acc[4] = {0.f, 0.f, 0.f, 0.f};
    for (int kc = 0; kc < RKk; kc += 64) {
        for (int i = tid; i < 1024; i += 256) {
            int r = i >> 6, k = i & 63;
            Ws[r][k] = W[(size_t)(j0 + r) * RKk + kc + k];
        }
        for (int i = tid; i < 4096; i += 256) {
            int bx = i >> 6, k = i & 63;
            Bs[bx][k] = g_BM[(size_t)bx * RKk + kc + k];
        }
        __syncthreads();
#pragma unroll 4
        for (int k = 0; k < 64; k++) {
            float w = Ws[rj][k];
            acc[0] = fmaf(w, Bs[bq + 0][k], acc[0]);
            acc[1] = fmaf(w, Bs[bq + 1][k], acc[1]);
            acc[2] = fmaf(w, Bs[bq + 2][k], acc[2]);
            acc[3] = fmaf(w, Bs[bq + 3][k], acc[3]);
        }
        __syncthreads();
    }
    float bv = bias[j0 + rj];
#pragma unroll
    for (int q = 0; q < 4; q++)
        g_hid[((size_t)head * Bb + bq + q) * MHh + j0 + rj] = fmaxf(acc[q] + bv, 0.f);
}

// ---- decode: grid (B, 3), 64 threads
__global__ void __launch_bounds__(64) k_dec(const float* __restrict__ Wdet,  const float* __restrict__ bdet,
                                            const float* __restrict__ Wdprt, const float* __restrict__ bdprt,
                                            const float* __restrict__ Wdpop, const float* __restrict__ bdpop,
                                            float* __restrict__ dout) {
    int b = blockIdx.x, head = blockIdx.y;
    int tid = threadIdx.x;
    const float* Wd; const float* bd; int N; int off;
    if (head == 0)      { Wd = Wdet;  bd = bdet;  N = 50; off = ET_OFF;   }
    else if (head == 1) { Wd = Wdprt; bd = bdprt; N = 12; off = PRT_OFF;  }
    else                { Wd = Wdpop; bd = bdpop; N = 8;  off = POPT_OFF; }
    __shared__ float sh[MHh];
    for (int k = tid; k < MHh; k += 64)
        sh[k] = g_hid[((size_t)head * Bb + b) * MHh + k];
    __syncthreads();
    if (tid < N) {
        float s = bd[tid];
        const float* wr = Wd + (size_t)tid * MHh;
        for (int k = 0; k < MHh; k++) s = fmaf(sh[k], wr[k], s);
        dout[off + b * N + tid] = s;
    }
}

extern "C" void kernel_launch(void* const* d_in, const int* in_sizes, int n_in,
                              void* d_out, int out_size) {
    const int*   ids   = (const int*)d_in[0];
    const int*   lens  = (const int*)d_in[1];
    const float* h0    = (const float*)d_in[2];
    const float* c0    = (const float*)d_in[3];
    const float* emb   = (const float*)d_in[4];
    const float* Wihf  = (const float*)d_in[5];
    const float* Whhf  = (const float*)d_in[6];
    const float* Wihb  = (const float*)d_in[7];
    const float* Whhb  = (const float*)d_in[8];
    const float* S1    = (const float*)d_in[9];
    const float* S2    = (const float*)d_in[10];
    const float* Wet   = (const float*)d_in[11];
    const float* bet   = (const float*)d_in[12];
    const float* Wdet  = (const float*)d_in[13];
    const float* bdet  = (const float*)d_in[14];
    const float* Wprt  = (const float*)d_in[15];
    const float* bprt  = (const float*)d_in[16];
    const float* Wdprt = (const float*)d_in[17];
    const float* bdprt = (const float*)d_in[18];
    const float* Wpop  = (const float*)d_in[19];
    const float* bpop  = (const float*)d_in[20];
    const float* Wdpop = (const float*)d_in[21];
    const float* bdpop = (const float*)d_in[22];
    float* dout = (float*)d_out;

    static int smem_set = 0;
    if (!smem_set) {
        cudaFuncSetAttribute(k_lstm, cudaFuncAttributeMaxDynamicSharedMemorySize,
                             LSTM_SMEM_FLOATS * 4);
        smem_set = 1;
    }

    k_transpose<<<dim3(16, 2), dim3(32, 8)>>>(S1);
    k_gemm_xw<<<dim3(8, 512, 2), 256>>>(ids, emb, Wihf, Wihb, lens);
    k_lstm<<<dim3(64, 2), 256, LSTM_SMEM_FLOATS * 4>>>(Whhf, Whhb, h0, c0, lens, dout);
    k_s2<<<4096, 256>>>(S2, lens);
    k_softmax<<<dim3(Rr, Bb), 256>>>(lens, dout);
    k_M<<<Bb, 512>>>(lens, dout);
    k_aat<<<Bb, 256>>>(lens, dout);
    k_pen<<<1, 64>>>(dout);
    k_hid<<<96, 256>>>(Wet, bet, Wprt, bprt, Wpop, bpop);
    k_dec<<<dim3(Bb, 3), 64>>>(Wdet, bdet, Wdprt, bdprt, Wdpop, bdpop, dout);
}